// round 11
// baseline (speedup 1.0000x reference)
#include <cuda_runtime.h>

#define Wd    1024
#define Hd    1024
#define RPB   8
#define NBLK2 1024                // blocks; each handles strips b and b+1024
#define TPB   256                 // 256 threads * 4 floats = 1024 = one row

// 1 / (16 * 1024 * 1024) = 2^-24, exact power of two -> exact scaling
#define INV_N 5.9604644775390625e-8f

__global__ void bce_zero_kernel(float* __restrict__ out) {
    if (threadIdx.x == 0) out[0] = 0.0f;
}

__device__ __forceinline__ unsigned bits4(float4 t) {
    unsigned m = 0u;
    if (t.x > 0.5f) m |= 1u;
    if (t.y > 0.5f) m |= 2u;
    if (t.z > 0.5f) m |= 4u;
    if (t.w > 0.5f) m |= 8u;
    return m;
}

__global__ __launch_bounds__(TPB)
void bce_main_kernel(const float* __restrict__ pred,
                     const float* __restrict__ tgt,
                     float* __restrict__ out) {
    const int x4   = threadIdx.x * 4;      // column of this thread's float4
    const int lane = threadIdx.x & 31;
    const bool has_left  = (x4 > 0);
    const bool has_right = (x4 + 4 < Wd);

    const int r0A = blockIdx.x * RPB;             // strip A first row
    const int r0B = (blockIdx.x + NBLK2) * RPB;   // strip B, 8 MB away
    // r0B - r0A = 8192 rows = multiple of Hd -> same row-within-image
    const int y0 = r0A & (Hd - 1);

    const float* tA = tgt  + (size_t)r0A * Wd + x4;
    const float* tB = tgt  + (size_t)r0B * Wd + x4;
    const float* pA = pred + (size_t)r0A * Wd + x4;
    const float* pB = pred + (size_t)r0B * Wd + x4;

    // Load one target row -> 4-bit occupancy mask m (out-param) and 4-bit
    // horizontal 3-max mask (return). Neighbor bits via shfl; warp-edge lanes
    // fall back to a scalar L1-hit load.
    auto hrow = [&](const float* p, unsigned& m) -> unsigned {
        float4 t4 = *reinterpret_cast<const float4*>(p);
        m = bits4(t4);
        unsigned ml = __shfl_up_sync(0xffffffffu, m, 1);
        unsigned mr = __shfl_down_sync(0xffffffffu, m, 1);
        unsigned l = (lane == 0)
            ? ((has_left  && __ldg(p - 1) > 0.5f) ? 1u : 0u)
            : ((ml >> 3) & 1u);
        unsigned r = (lane == 31)
            ? ((has_right && __ldg(p + 4) > 0.5f) ? 8u : 0u)
            : ((mr & 1u) << 3);
        return (m | (m << 1) | (m >> 1) | l | r) & 0xFu;
    };

    // depth-2 pipelined rolling window: rows r-1, r, r+1, r+2 per strip
    unsigned hAm1, hA0, hAp1, hAp2, mA, mA1, mA2;
    unsigned hBm1, hB0, hBp1, hBp2, mB, mB1, mB2;
    unsigned dummy;

    // prologue: rows r0-1, r0, r0+1 masks; pred row r0 prefetch
    if (y0 > 0) {
        hAm1 = hrow(tA - Wd, dummy);
        hBm1 = hrow(tB - Wd, dummy);
    } else {
        hAm1 = 0u; hBm1 = 0u;
    }
    hA0  = hrow(tA, mA);
    hB0  = hrow(tB, mB);
    hAp1 = hrow(tA + Wd, mA1);     // row r0+1 always exists (y0 <= Hd-RPB)
    hBp1 = hrow(tB + Wd, mB1);

    float4 p4A = *reinterpret_cast<const float4*>(pA);
    float4 p4B = *reinterpret_cast<const float4*>(pB);

    float acc = 0.0f;

    #pragma unroll
    for (int i = 0; i < RPB; ++i) {
        const int y = y0 + i;

        // ---- front-batched loads for FUTURE iterations (nothing consumed
        //      this iteration): tgt row r+2 masks, pred row r+1 ----
        if (y < Hd - 2) {
            hAp2 = hrow(tA + 2 * Wd, mA2);
            hBp2 = hrow(tB + 2 * Wd, mB2);
        } else {
            hAp2 = 0u; mA2 = 0u;
            hBp2 = 0u; mB2 = 0u;
        }
        float4 p4An, p4Bn;
        if (i < RPB - 1) {
            p4An = *reinterpret_cast<const float4*>(pA + Wd);
            p4Bn = *reinterpret_cast<const float4*>(pB + Wd);
        }

        // ---- compute row r from registers filled >= 1 iteration ago ----
        const unsigned dilA = hAm1 | hA0 | hAp1;   // vertical max = bit OR
        const unsigned dilB = hBm1 | hB0 | hBp1;

        {
            float xs[4] = {p4A.x, p4A.y, p4A.z, p4A.w};
            #pragma unroll
            for (int j = 0; j < 4; ++j) {
                float x = xs[j];
                bool tb = (mA   >> j) & 1u;
                bool db = (dilA >> j) & 1u;
                float w = tb ? 20.0f : (db ? 5.0f : 1.0f);
                float a  = fabsf(x);
                float sp = __logf(1.0f + __expf(-a));   // log1p(exp(-|x|))
                float base = fmaxf(x, 0.0f) - (tb ? x : 0.0f) + sp;
                acc = fmaf(w, base, acc);
            }
        }
        {
            float xs[4] = {p4B.x, p4B.y, p4B.z, p4B.w};
            #pragma unroll
            for (int j = 0; j < 4; ++j) {
                float x = xs[j];
                bool tb = (mB   >> j) & 1u;
                bool db = (dilB >> j) & 1u;
                float w = tb ? 20.0f : (db ? 5.0f : 1.0f);
                float a  = fabsf(x);
                float sp = __logf(1.0f + __expf(-a));
                float base = fmaxf(x, 0.0f) - (tb ? x : 0.0f) + sp;
                acc = fmaf(w, base, acc);
            }
        }

        // ---- roll windows, march pointers ----
        hAm1 = hA0; hA0 = hAp1; hAp1 = hAp2; mA = mA1; mA1 = mA2;
        hBm1 = hB0; hB0 = hBp1; hBp1 = hBp2; mB = mB1; mB1 = mB2;
        if (i < RPB - 1) { p4A = p4An; p4B = p4Bn; }
        tA += Wd; tB += Wd; pA += Wd; pB += Wd;
    }

    // ---- block reduction (fixed tree order), then one relaxed atomic ----
    #pragma unroll
    for (int off = 16; off > 0; off >>= 1)
        acc += __shfl_down_sync(0xffffffffu, acc, off);

    __shared__ float smem[TPB / 32];
    const int wid = threadIdx.x >> 5;
    if (lane == 0) smem[wid] = acc;
    __syncthreads();
    if (threadIdx.x == 0) {
        acc = smem[0];
        #pragma unroll
        for (int k = 1; k < TPB / 32; ++k) acc += smem[k];
        // exact 2^-24 scale; relaxed fp32 atomic (REDG) — no fence, no acquire
        atomicAdd(out, acc * INV_N);
    }
}

extern "C" void kernel_launch(void* const* d_in, const int* in_sizes, int n_in,
                              void* d_out, int out_size) {
    const float* pred = (const float*)d_in[0];
    const float* tgt  = (const float*)d_in[1];
    float* out = (float*)d_out;

    bce_zero_kernel<<<1, 32>>>(out);
    bce_main_kernel<<<NBLK2, TPB>>>(pred, tgt, out);
}

// round 13
// speedup vs baseline: 1.5130x; 1.5130x over previous
#include <cuda_runtime.h>

#define Wd   1024
#define Hd   1024
#define RPB  8
#define NBLK 2048                 // single strip per block
#define TPB  256                  // 256 threads * 4 floats = 1024 = one row

// 1 / (16 * 1024 * 1024) = 2^-24, exact power of two -> exact scaling
#define INV_N 5.9604644775390625e-8f

__global__ void bce_zero_kernel(float* __restrict__ out) {
    if (threadIdx.x == 0) out[0] = 0.0f;
}

struct RawRow { float4 t4; float l, r; };

__device__ __forceinline__ unsigned bits4(float4 t) {
    unsigned m = 0u;
    if (t.x > 0.5f) m |= 1u;
    if (t.y > 0.5f) m |= 2u;
    if (t.z > 0.5f) m |= 4u;
    if (t.w > 0.5f) m |= 8u;
    return m;
}

__global__ __launch_bounds__(TPB)
void bce_main_kernel(const float* __restrict__ pred,
                     const float* __restrict__ tgt,
                     float* __restrict__ out) {
    const int x4   = threadIdx.x * 4;      // column of this thread's float4
    const int lane = threadIdx.x & 31;
    const bool has_left  = (x4 > 0);
    const bool has_right = (x4 + 4 < Wd);

    const int r0 = blockIdx.x * RPB;       // first global row for this block
    const int y0 = r0 & (Hd - 1);          // row within image (RPB divides Hd)

    const float* tp = tgt  + (size_t)r0 * Wd + x4;
    const float* pp = pred + (size_t)r0 * Wd + x4;

    // raw load: float4 + edge scalars. NO processing here — pure LDG issue.
    auto load_raw = [&](const float* p, RawRow& rr) {
        rr.t4 = *reinterpret_cast<const float4*>(p);
        rr.l = (lane == 0  && has_left ) ? __ldg(p - 1) : 0.0f;
        rr.r = (lane == 31 && has_right) ? __ldg(p + 4) : 0.0f;
    };

    // process a buffered raw row (loaded >= 1 iteration ago):
    // occupancy mask m (out) + horizontal 3-max mask (return)
    auto process = [&](const RawRow& rr, unsigned& m) -> unsigned {
        m = bits4(rr.t4);
        unsigned ml = __shfl_up_sync(0xffffffffu, m, 1);
        unsigned mr = __shfl_down_sync(0xffffffffu, m, 1);
        unsigned l = (lane == 0)  ? (rr.l > 0.5f ? 1u : 0u) : ((ml >> 3) & 1u);
        unsigned r = (lane == 31) ? (rr.r > 0.5f ? 8u : 0u) : ((mr & 1u) << 3);
        return (m | (m << 1) | (m >> 1) | l | r) & 0xFu;
    };

    // ---- prologue ----
    unsigned hm1, h0, hp1, m, m1, dummy;
    RawRow traw;                      // raw tgt row r+1 (pipeline buffer)

    if (y0 > 0) {
        RawRow t; load_raw(tp - Wd, t);
        hm1 = process(t, dummy);
    } else hm1 = 0u;
    {
        RawRow t; load_raw(tp, t);
        h0 = process(t, m);
    }
    load_raw(tp + Wd, traw);          // row r0+1 always exists (y0 <= Hd-RPB)
    float4 p4 = *reinterpret_cast<const float4*>(pp);

    float acc = 0.0f;

    #pragma unroll
    for (int i = 0; i < RPB; ++i) {
        const int y = y0 + i;

        // ---- issue loads consumed NEXT iteration (fire-and-forget) ----
        RawRow tnew;
        if (y < Hd - 2) {
            load_raw(tp + 2 * Wd, tnew);
        } else {
            tnew.t4 = make_float4(0.f, 0.f, 0.f, 0.f);
            tnew.l = 0.f; tnew.r = 0.f;
        }
        float4 p4n;
        if (i < RPB - 1)
            p4n = *reinterpret_cast<const float4*>(pp + Wd);

        // ---- process buffered row r+1 (its LDG landed an iteration ago) ----
        hp1 = process(traw, m1);

        const unsigned dil = hm1 | h0 | hp1;   // vertical max = bit OR

        // ---- loss for row r ----
        {
            float xs[4] = {p4.x, p4.y, p4.z, p4.w};
            #pragma unroll
            for (int j = 0; j < 4; ++j) {
                float x = xs[j];
                bool tb = (m   >> j) & 1u;
                bool db = (dil >> j) & 1u;
                float w = tb ? 20.0f : (db ? 5.0f : 1.0f);
                float a  = fabsf(x);
                float sp = __logf(1.0f + __expf(-a));   // log1p(exp(-|x|))
                float base = fmaxf(x, 0.0f) - (tb ? x : 0.0f) + sp;
                acc = fmaf(w, base, acc);
            }
        }

        // ---- roll pipeline ----
        hm1 = h0; h0 = hp1; m = m1;
        traw = tnew;
        if (i < RPB - 1) p4 = p4n;
        tp += Wd; pp += Wd;
    }

    // ---- block reduction (fixed tree order), then one relaxed atomic ----
    #pragma unroll
    for (int off = 16; off > 0; off >>= 1)
        acc += __shfl_down_sync(0xffffffffu, acc, off);

    __shared__ float smem[TPB / 32];
    const int wid = threadIdx.x >> 5;
    if (lane == 0) smem[wid] = acc;
    __syncthreads();
    if (threadIdx.x == 0) {
        acc = smem[0];
        #pragma unroll
        for (int k = 1; k < TPB / 32; ++k) acc += smem[k];
        // exact 2^-24 scale; relaxed fp32 atomic (REDG) — no fence, no acquire
        atomicAdd(out, acc * INV_N);
    }
}

extern "C" void kernel_launch(void* const* d_in, const int* in_sizes, int n_in,
                              void* d_out, int out_size) {
    const float* pred = (const float*)d_in[0];
    const float* tgt  = (const float*)d_in[1];
    float* out = (float*)d_out;

    bce_zero_kernel<<<1, 32>>>(out);
    bce_main_kernel<<<NBLK, TPB>>>(pred, tgt, out);
}